// round 15
// baseline (speedup 1.0000x reference)
#include <cuda_runtime.h>
#include <math_constants.h>

#define B 8
#define NPTS 4096
#define DIM 64
#define KNB 8
#define NLAYERS 12

#define KNN_SPLIT 2
#define KNN_HALF (NPTS / KNN_SPLIT)        // 2048
#define KNN_QB 128                          // queries per block
#define KNN_TPB (KNN_QB * 2)                // 256: each query has 2 threads (one per half)
#define KNN_SMEM (4 * NPTS * 4 + 2 * KNN_QB * 4)   // SoA xyzw + tau[2][QB]

// ---------------- device-global scratch (no dynamic allocation allowed) -------------
__device__ float4 g_xyz4[B * NPTS];                     // (x,y,z,|x|^2) per point
__device__ int    g_idx [B * NPTS * KNB];               // knn indices [b][n][k]
__device__ float  g_knn_d[B * NPTS * KNN_SPLIT * KNB];  // partial top-8 distances
__device__ int    g_knn_i[B * NPTS * KNN_SPLIT * KNB];  // partial top-8 indices
__device__ __align__(16) float g_pm0[B * NPTS * DIM];   // raw features, point-major (ping)
__device__ __align__(16) float g_pm1[B * NPTS * DIM];   // raw features, point-major (pong)
__device__ float  g_wt  [NLAYERS * DIM * DIM];          // W^T per layer: wt[d][c] = w[c][d]
__device__ double g_acc[NLAYERS * 2 * DIM];             // per-layer [l][c]=sum, [l][DIM+c]=sumsq

// ---------------- packed f32x2 helpers (per-lane rounding == scalar fmaf/add) -------
__device__ __forceinline__ unsigned long long f2pk(float lo, float hi) {
    unsigned long long r;
    asm("mov.b64 %0, {%1, %2};" : "=l"(r) : "f"(lo), "f"(hi));
    return r;
}
__device__ __forceinline__ void f2upk(float& lo, float& hi, unsigned long long v) {
    asm("mov.b64 {%0, %1}, %2;" : "=f"(lo), "=f"(hi) : "l"(v));
}
__device__ __forceinline__ unsigned long long f2add(unsigned long long a, unsigned long long b) {
    unsigned long long r;
    asm("add.rn.f32x2 %0, %1, %2;" : "=l"(r) : "l"(a), "l"(b));
    return r;
}
__device__ __forceinline__ unsigned long long f2fma(unsigned long long a, unsigned long long b,
                                                    unsigned long long c) {
    unsigned long long r;
    asm("fma.rn.f32x2 %0, %1, %2, %3;" : "=l"(r) : "l"(a), "l"(b), "l"(c));
    return r;
}

// ---------------- prep: pack xyz + squared norm ----------------
__global__ void prep_xyz_kernel(const float* __restrict__ xyz) {
    int i = blockIdx.x * blockDim.x + threadIdx.x;
    if (i >= B * NPTS) return;
    int b = i / NPTS, p = i % NPTS;
    const float* base = xyz + (size_t)b * 3 * NPTS;
    float x = base[p], y = base[NPTS + p], z = base[2 * NPTS + p];
    float sq = x * x + y * y + z * z;
    g_xyz4[i] = make_float4(x, y, z, sq);
}

// ---------------- prep: transpose conv weights ----------------
__global__ void prep_wt_kernel(const float* __restrict__ w) {
    int i = blockIdx.x * blockDim.x + threadIdx.x;
    if (i >= NLAYERS * DIM * DIM) return;
    int l = i / (DIM * DIM), r = i % (DIM * DIM);
    int d = r / DIM, c = r % DIM;
    g_wt[i] = w[l * DIM * DIM + c * DIM + d];
}

// ---------------- zero all per-layer stat accumulators (per graph replay) ----------
__global__ void zero_acc_kernel() {
    int i = blockIdx.x * blockDim.x + threadIdx.x;
    if (i < NLAYERS * 2 * DIM) g_acc[i] = 0.0;
}

// ---------------- KNN pass 1: per-half top-8 with cross-half threshold sharing -------
// Block handles KNN_QB queries; thread (qloc, half) scans its half's 2048 candidates.
// Each thread publishes its running 8th-best (tau); the sibling half prunes groups
// provably outside the GLOBAL top-8 (any part's running 8th-best >= global 8th-best).
// Group guard: m < bd[7] && m <= tau_other  ('<=' keeps boundary-equal candidates,
// so the merged output is exactly the reference top-8, independent of timing).
__global__ void __launch_bounds__(KNN_TPB) knn_kernel() {
    extern __shared__ float smem[];
    float* sx = smem;
    float* sy = smem + NPTS;
    float* sz = smem + 2 * NPTS;
    float* sw = smem + 3 * NPTS;
    float* tau = smem + 4 * NPTS;        // tau[half][qloc], 2*KNN_QB floats

    int b = blockIdx.y;
    int t = threadIdx.x;
    int qloc = t & (KNN_QB - 1);
    int half = t >> 7;                   // KNN_QB == 128
    int q = blockIdx.x * KNN_QB + qloc;
    int base = half * KNN_HALF;
    const float4* xb = g_xyz4 + b * NPTS;

    for (int i = t; i < NPTS; i += KNN_TPB) {
        float4 c = xb[i];
        sx[i] = c.x; sy[i] = c.y; sz[i] = c.z; sw[i] = c.w;
    }
    tau[t >= KNN_QB ? t : t] = CUDART_INF_F;   // each of 256 threads owns one slot
    // (t in [0,256) covers tau[0..255] exactly)

    float4 me = xb[q];
    float nx = -2.f * me.x, ny = -2.f * me.y, nz = -2.f * me.z;
    float sqi = me.w;
    unsigned long long NX2 = f2pk(nx, nx), NY2 = f2pk(ny, ny), NZ2 = f2pk(nz, nz);
    unsigned long long SQ2 = f2pk(sqi, sqi);

    float bd[KNB];
    int   bi[KNB];
#pragma unroll
    for (int k = 0; k < KNB; k++) { bd[k] = CUDART_INF_F; bi[k] = -1; }
    __syncthreads();

    volatile float* tau_o = tau + (1 - half) * KNN_QB + qloc;  // sibling's threshold
    volatile float* tau_m = tau + half * KNN_QB + qloc;        // mine

#define TRYINS(dv, jv)                                                    \
    if ((dv) < bd[KNB - 1]) {                                             \
        bd[KNB - 1] = (dv); bi[KNB - 1] = (jv);                           \
        _Pragma("unroll")                                                 \
        for (int k = KNB - 1; k >= 1; k--) {                              \
            if (bd[k] < bd[k - 1]) {                                      \
                float td = bd[k]; bd[k] = bd[k - 1]; bd[k - 1] = td;      \
                int   ti = bi[k]; bi[k] = bi[k - 1]; bi[k - 1] = ti;      \
            }                                                             \
        }                                                                 \
    }

    for (int j = 0; j < KNN_HALF; j += 4) {
        float4 x4 = *(const float4*)(sx + base + j);
        float4 y4 = *(const float4*)(sy + base + j);
        float4 z4 = *(const float4*)(sz + base + j);
        float4 w4 = *(const float4*)(sw + base + j);
        // pair 0,1  (chain bitwise-identical to scalar fmaf version)
        unsigned long long t01 = f2add(f2pk(w4.x, w4.y), SQ2);
        t01 = f2fma(f2pk(z4.x, z4.y), NZ2, t01);
        t01 = f2fma(f2pk(y4.x, y4.y), NY2, t01);
        t01 = f2fma(f2pk(x4.x, x4.y), NX2, t01);
        // pair 2,3
        unsigned long long t23 = f2add(f2pk(w4.z, w4.w), SQ2);
        t23 = f2fma(f2pk(z4.z, z4.w), NZ2, t23);
        t23 = f2fma(f2pk(y4.z, y4.w), NY2, t23);
        t23 = f2fma(f2pk(x4.z, x4.w), NX2, t23);
        float d0, d1, d2, d3;
        f2upk(d0, d1, t01);
        f2upk(d2, d3, t23);
        float m = fminf(fminf(d0, d1), fminf(d2, d3));
        float to = *tau_o;                         // stale read is safe (larger)
        if (m < bd[KNB - 1] && m <= to) {
            TRYINS(d0, base + j + 0);
            TRYINS(d1, base + j + 1);
            TRYINS(d2, base + j + 2);
            TRYINS(d3, base + j + 3);
            *tau_m = bd[KNB - 1];
        }
    }
#undef TRYINS

    size_t o = ((size_t)(b * NPTS + q) * KNN_SPLIT + half) * KNB;
#pragma unroll
    for (int k = 0; k < KNB; k++) { g_knn_d[o + k] = bd[k]; g_knn_i[o + k] = bi[k]; }
}

// ---------------- KNN pass 2: merge the two sorted top-8 lists ----------------
// Half-0 indices are all < half-1 indices, so 'dA <= dB -> take A' preserves
// lower-index-first on ties (matches reference top_k tie order).
__global__ void knn_merge_kernel() {
    int i = blockIdx.x * blockDim.x + threadIdx.x;
    if (i >= B * NPTS) return;
    size_t o = (size_t)i * KNN_SPLIT * KNB;
    const float* dA = g_knn_d + o;
    const float* dB = dA + KNB;
    const int*   iA = g_knn_i + o;
    const int*   iB = iA + KNB;
    int a = 0, c = 0;
    int* orow = g_idx + (size_t)i * KNB;
#pragma unroll
    for (int k = 0; k < KNB; k++) {
        bool takeA = (c >= KNB) || (a < KNB && dA[a] <= dB[c]);
        orow[k] = takeA ? iA[a] : iB[c];
        if (takeA) a++; else c++;
    }
}

// ---------------- layer-0 stats: fp32 partials -> double atomics ----------------
__global__ void __launch_bounds__(256) stats0_kernel(const float* __restrict__ p) {
    int c = blockIdx.x, b = blockIdx.y;
    const float* row = p + ((size_t)b * DIM + c) * NPTS;
    float s = 0.f, q = 0.f;
    for (int i = threadIdx.x; i < NPTS; i += 256) {
        float v = row[i];
        s += v; q = fmaf(v, v, q);
    }
    __shared__ float ss[256], qq[256];
    ss[threadIdx.x] = s; qq[threadIdx.x] = q;
    __syncthreads();
    for (int o = 128; o > 0; o >>= 1) {
        if (threadIdx.x < o) { ss[threadIdx.x] += ss[threadIdx.x + o]; qq[threadIdx.x] += qq[threadIdx.x + o]; }
        __syncthreads();
    }
    if (threadIdx.x == 0) {
        atomicAdd(&g_acc[c],       (double)ss[0]);
        atomicAdd(&g_acc[DIM + c], (double)qq[0]);
    }
}

// ---------------- layer-0 prep: transpose points to point-major raw ----------------
__global__ void __launch_bounds__(256) transpose_kernel(const float* __restrict__ p,
                                                        float* __restrict__ pm) {
    __shared__ float tile[DIM][65];
    int b = blockIdx.y;
    int i0 = blockIdx.x * 64;
    int t = threadIdx.x;
#pragma unroll
    for (int k = 0; k < 16; k++) {
        int e = t + k * 256;
        int c = e >> 6, i = e & 63;
        tile[c][i] = p[((size_t)b * DIM + c) * NPTS + i0 + i];
    }
    __syncthreads();
#pragma unroll
    for (int k = 0; k < 16; k++) {
        int e = t + k * 256;
        int i = e >> 6, c = e & 63;
        pm[((size_t)b * NPTS + i0 + i) * DIM + c] = tile[c][i];
    }
}

// ==== fused layer: BN fold + gather(normalize+lrelu on the fly) + matmul + residual
//      + next-layer stats + point-major raw output. Residual comes from pm_in;
//      channel-major output (pout) is written only on the last layer. ====
__global__ void __launch_bounds__(256) fused_block_kernel(
        const float* __restrict__ pm_in,  // point-major raw prev (gather + residual)
        float* __restrict__ pout,         // channel-major raw out (last layer only)
        float* __restrict__ pm_out,       // point-major raw out (null on last layer)
        const float* __restrict__ wt,
        const float* __restrict__ bias,
        const double* __restrict__ accin, // stats of prev raw -> scale/shift
        double* __restrict__ accout,      // stats accum for out (null on last layer)
        const float* __restrict__ gamma,
        const float* __restrict__ beta) {
    __shared__ float Wt[DIM][DIM];   // Wt[d][c]
    __shared__ float S[64][65];      // phase 1: S[i][d] = aggregated h / (K+1); phase 2: [c][i]
    __shared__ float s_sc[DIM], s_sh[DIM];
    int b = blockIdx.y;
    int i0 = blockIdx.x * 64;
    int t = threadIdx.x;

    // prologue: fold BN stats into scale/shift (identical math to before)
    if (t < DIM) {
        double s = accin[t], q = accin[DIM + t];
        double mean = s / (double)(B * NPTS);
        double var  = q / (double)(B * NPTS) - mean * mean;
        float rstd = rsqrtf((float)var + 1e-5f);
        float sc = gamma[t] * rstd;
        s_sc[t] = sc;
        s_sh[t] = beta[t] - (float)mean * sc;
    }
    // stage W^T (consumed after the post-aggregation sync)
#pragma unroll
    for (int k = 0; k < 16; k++) {
        int e = t + k * 256;
        ((float*)Wt)[e] = wt[e];
    }
    __syncthreads();   // s_sc/s_sh ready for aggregation

    // aggregation: warp handles 8 points as 4 half-warp pairs; 16 lanes x float4 = 256B row.
    // h = lrelu(raw*sc+sh) applied at gather time (bitwise-identical to precomputed h).
    int warp = t >> 5, lane = t & 31;
    int half = lane >> 4, l16 = lane & 15;
    const float inv = 1.f / (float)(KNB + 1);
    float4 sc4 = *(const float4*)&s_sc[4 * l16];
    float4 sh4 = *(const float4*)&s_sh[4 * l16];
    for (int pp = 0; pp < 8; pp += 2) {
        int il = warp * 8 + pp + half;
        int ig = i0 + il;
        const int4* ir = (const int4*)(g_idx + ((size_t)b * NPTS + ig) * KNB);
        int4 ja = ir[0], jb = ir[1];
        int js[9] = { ig, ja.x, ja.y, ja.z, ja.w, jb.x, jb.y, jb.z, jb.w };
        float a0 = 0.f, a1 = 0.f, a2 = 0.f, a3 = 0.f;
#pragma unroll
        for (int k = 0; k < 9; k++) {
            const float4* row = (const float4*)(pm_in + ((size_t)b * NPTS + js[k]) * DIM);
            float4 v = row[l16];
            float h0 = fmaf(v.x, sc4.x, sh4.x); h0 = (h0 >= 0.f) ? h0 : 0.01f * h0;
            float h1 = fmaf(v.y, sc4.y, sh4.y); h1 = (h1 >= 0.f) ? h1 : 0.01f * h1;
            float h2 = fmaf(v.z, sc4.z, sh4.z); h2 = (h2 >= 0.f) ? h2 : 0.01f * h2;
            float h3 = fmaf(v.w, sc4.w, sh4.w); h3 = (h3 >= 0.f) ? h3 : 0.01f * h3;
            a0 += h0; a1 += h1; a2 += h2; a3 += h3;
        }
        S[il][4 * l16 + 0] = a0 * inv;
        S[il][4 * l16 + 1] = a1 * inv;
        S[il][4 * l16 + 2] = a2 * inv;
        S[il][4 * l16 + 3] = a3 * inv;
    }
    __syncthreads();

    // matmul: thread handles point i = t%64, channels [c0, c0+16)
    int g  = t >> 6;
    int i  = t & 63;
    int c0 = g * 16;

    // preload residual raw (center row, L1-hot from aggregation) + bias
    float raw[16], bs[16];
    {
        const float4* rr = (const float4*)(pm_in + ((size_t)b * NPTS + i0 + i) * DIM + c0);
        *(float4*)&raw[0]  = rr[0];
        *(float4*)&raw[4]  = rr[1];
        *(float4*)&raw[8]  = rr[2];
        *(float4*)&raw[12] = rr[3];
        const float4* bb = (const float4*)(bias + c0);
        *(float4*)&bs[0]  = bb[0];
        *(float4*)&bs[4]  = bb[1];
        *(float4*)&bs[8]  = bb[2];
        *(float4*)&bs[12] = bb[3];
    }

    float acc[16];
#pragma unroll
    for (int j = 0; j < 16; j++) acc[j] = 0.f;
#pragma unroll 4
    for (int d = 0; d < DIM; d++) {
        float sv = S[i][d];
        const float4* wr = (const float4*)(&Wt[d][c0]);
#pragma unroll
        for (int q = 0; q < 4; q++) {
            float4 w4 = wr[q];
            acc[4 * q + 0] = fmaf(sv, w4.x, acc[4 * q + 0]);
            acc[4 * q + 1] = fmaf(sv, w4.y, acc[4 * q + 1]);
            acc[4 * q + 2] = fmaf(sv, w4.z, acc[4 * q + 2]);
            acc[4 * q + 3] = fmaf(sv, w4.w, acc[4 * q + 3]);
        }
    }
    // combine: v = (conv + bias) + residual  (same order as before)
#pragma unroll
    for (int j = 0; j < 16; j++) acc[j] = acc[j] + bs[j] + raw[j];

    if (pout != nullptr) {
        // last layer: channel-major output, coalesced across i
#pragma unroll
        for (int j = 0; j < 16; j++) {
            int c = c0 + j;
            pout[((size_t)b * DIM + c) * NPTS + i0 + i] = acc[j];
        }
    }

    if (pm_out != nullptr) {
        __syncthreads();   // all matmul reads of S done before reuse
#pragma unroll
        for (int j = 0; j < 16; j++) S[c0 + j][i] = acc[j];
        __syncthreads();

        // next-layer stats: per-channel partial sums -> global double accumulators
        if (accout != nullptr && t < DIM) {
            float s0 = 0.f, s1 = 0.f, q0 = 0.f, q1 = 0.f;
#pragma unroll
            for (int i2 = 0; i2 < 64; i2 += 2) {
                float a = S[t][i2], bb2 = S[t][i2 + 1];
                s0 += a; s1 += bb2;
                q0 = fmaf(a, a, q0); q1 = fmaf(bb2, bb2, q1);
            }
            atomicAdd(&accout[t],       (double)(s0 + s1));
            atomicAdd(&accout[DIM + t], (double)(q0 + q1));
        }

        // point-major raw output (coalesced via smem)
#pragma unroll
        for (int k = 0; k < 16; k++) {
            int e = t + k * 256;
            int ii = e >> 6, cc = e & 63;
            pm_out[((size_t)b * NPTS + i0 + ii) * DIM + cc] = S[cc][ii];
        }
    }
}

// ---------------- launch ----------------
extern "C" void kernel_launch(void* const* d_in, const int* in_sizes, int n_in,
                              void* d_out, int out_size) {
    const float* xyz    = (const float*)d_in[0];
    const float* points = (const float*)d_in[1];
    const float* conv_w = (const float*)d_in[2];
    const float* conv_b = (const float*)d_in[3];
    const float* gamma  = (const float*)d_in[4];
    const float* beta   = (const float*)d_in[5];
    float* out = (float*)d_out;

    float *wtp, *pm0, *pm1;
    double* accp;
    cudaGetSymbolAddress((void**)&wtp,  g_wt);
    cudaGetSymbolAddress((void**)&pm0,  g_pm0);
    cudaGetSymbolAddress((void**)&pm1,  g_pm1);
    cudaGetSymbolAddress((void**)&accp, g_acc);

    cudaFuncSetAttribute(knn_kernel, cudaFuncAttributeMaxDynamicSharedMemorySize, KNN_SMEM);

    zero_acc_kernel<<<(NLAYERS * 2 * DIM + 255) / 256, 256>>>();
    prep_xyz_kernel<<<(B * NPTS + 255) / 256, 256>>>(xyz);
    prep_wt_kernel<<<(NLAYERS * DIM * DIM + 255) / 256, 256>>>(conv_w);
    knn_kernel<<<dim3(NPTS / KNN_QB, B), KNN_TPB, KNN_SMEM>>>();
    knn_merge_kernel<<<(B * NPTS + 255) / 256, 256>>>();
    stats0_kernel<<<dim3(DIM, B), 256>>>(points);
    transpose_kernel<<<dim3(NPTS / 64, B), 256>>>(points, pm0);

    const float* pm_cur = pm0;
    for (int l = 0; l < NLAYERS; l++) {
        bool last = (l == NLAYERS - 1);
        float* pout  = last ? out : nullptr;
        float* pm_nx = last ? nullptr : ((l & 1) ? pm0 : pm1);
        double* accout = last ? nullptr : (accp + (size_t)(l + 1) * 2 * DIM);
        fused_block_kernel<<<dim3(NPTS / 64, B), 256>>>(
            pm_cur, pout, pm_nx,
            wtp + (size_t)l * DIM * DIM, conv_b + l * DIM,
            accp + (size_t)l * 2 * DIM, accout,
            gamma + l * DIM, beta + l * DIM);
        pm_cur = pm_nx;
    }
}

// round 16
// speedup vs baseline: 1.3795x; 1.3795x over previous
#include <cuda_runtime.h>
#include <math_constants.h>

#define B 8
#define NPTS 4096
#define DIM 64
#define KNB 8
#define NLAYERS 12

#define KNN_SPLIT 2
#define CAND_PER_BLOCK (NPTS / KNN_SPLIT)   // 2048
#define KNN_TPB 128
#define NBINS 512                            // 8x8x8 morton bins

// ---------------- device-global scratch (no dynamic allocation allowed) -------------
__device__ float4 g_xyz4[B * NPTS];                     // (x,y,z,|x|^2) per point
__device__ int    g_idx [B * NPTS * KNB];               // knn indices [b][n][k]
__device__ float  g_knn_d[B * NPTS * KNN_SPLIT * KNB];  // partial top-8 distances
__device__ int    g_knn_i[B * NPTS * KNN_SPLIT * KNB];  // partial top-8 indices
__device__ int    g_key [B * NPTS];                     // spatial bin key per point
__device__ int    g_hist[B * NBINS];                    // per-batch bin histogram
__device__ int    g_off [B * NBINS];                    // per-batch bin offsets (consumed)
__device__ int    g_perm[B * NPTS];                     // spatially-sorted query order
__device__ float  g_pm0 [B * NPTS * DIM];               // raw features, point-major (ping)
__device__ float  g_pm1 [B * NPTS * DIM];               // raw features, point-major (pong)
__device__ float  g_bufA[B * DIM * NPTS];               // channel-major ping
__device__ float  g_bufB[B * DIM * NPTS];               // channel-major pong
__device__ float  g_wt  [NLAYERS * DIM * DIM];          // W^T per layer: wt[d][c] = w[c][d]
__device__ double g_acc[NLAYERS * 2 * DIM];             // per-layer [l][c]=sum, [l][DIM+c]=sumsq

// ---------------- packed f32x2 helpers (per-lane rounding == scalar fmaf/add) -------
__device__ __forceinline__ unsigned long long f2pk(float lo, float hi) {
    unsigned long long r;
    asm("mov.b64 %0, {%1, %2};" : "=l"(r) : "f"(lo), "f"(hi));
    return r;
}
__device__ __forceinline__ void f2upk(float& lo, float& hi, unsigned long long v) {
    asm("mov.b64 {%0, %1}, %2;" : "=f"(lo), "=f"(hi) : "l"(v));
}
__device__ __forceinline__ unsigned long long f2add(unsigned long long a, unsigned long long b) {
    unsigned long long r;
    asm("add.rn.f32x2 %0, %1, %2;" : "=l"(r) : "l"(a), "l"(b));
    return r;
}
__device__ __forceinline__ unsigned long long f2fma(unsigned long long a, unsigned long long b,
                                                    unsigned long long c) {
    unsigned long long r;
    asm("fma.rn.f32x2 %0, %1, %2, %3;" : "=l"(r) : "l"(a), "l"(b), "l"(c));
    return r;
}

// ---------------- prep: pack xyz + squared norm; spatial bin key + histogram --------
__global__ void zero_hist_kernel() {
    int i = blockIdx.x * blockDim.x + threadIdx.x;
    if (i < B * NBINS) g_hist[i] = 0;
}

__device__ __forceinline__ int morton9(int a, int b, int c) {
    int m = 0;
#pragma unroll
    for (int k = 0; k < 3; k++) {
        m |= ((a >> k) & 1) << (3 * k + 2);
        m |= ((b >> k) & 1) << (3 * k + 1);
        m |= ((c >> k) & 1) << (3 * k + 0);
    }
    return m;
}

__global__ void prep_xyz_kernel(const float* __restrict__ xyz) {
    int i = blockIdx.x * blockDim.x + threadIdx.x;
    if (i >= B * NPTS) return;
    int b = i / NPTS, p = i % NPTS;
    const float* base = xyz + (size_t)b * 3 * NPTS;
    float x = base[p], y = base[NPTS + p], z = base[2 * NPTS + p];
    float sq = x * x + y * y + z * z;
    g_xyz4[i] = make_float4(x, y, z, sq);
    // spatial bin (8 bins per axis over [-2, 2], clamped) -> 9-bit morton key
    int cx = min(7, max(0, (int)((x + 2.0f) * 2.0f)));
    int cy = min(7, max(0, (int)((y + 2.0f) * 2.0f)));
    int cz = min(7, max(0, (int)((z + 2.0f) * 2.0f)));
    int key = morton9(cx, cy, cz);
    g_key[i] = key;
    atomicAdd(&g_hist[b * NBINS + key], 1);
}

// per-batch exclusive prefix over NBINS bins (one block per batch)
__global__ void __launch_bounds__(NBINS) prefix_kernel() {
    __shared__ int s[NBINS];
    int b = blockIdx.x, t = threadIdx.x;
    int orig = g_hist[b * NBINS + t];
    s[t] = orig;
    __syncthreads();
    for (int o = 1; o < NBINS; o <<= 1) {
        int u = (t >= o) ? s[t - o] : 0;
        __syncthreads();
        s[t] += u;
        __syncthreads();
    }
    g_off[b * NBINS + t] = s[t] - orig;   // exclusive
}

// scatter points into spatial order (intra-bin order nondeterministic — harmless,
// since each query's KNN result is independent of which lane computes it)
__global__ void scatter_kernel() {
    int i = blockIdx.x * blockDim.x + threadIdx.x;
    if (i >= B * NPTS) return;
    int b = i / NPTS, p = i % NPTS;
    int key = g_key[i];
    int pos = atomicAdd(&g_off[b * NBINS + key], 1);
    g_perm[b * NPTS + pos] = p;
}

// ---------------- prep: transpose conv weights ----------------
__global__ void prep_wt_kernel(const float* __restrict__ w) {
    int i = blockIdx.x * blockDim.x + threadIdx.x;
    if (i >= NLAYERS * DIM * DIM) return;
    int l = i / (DIM * DIM), r = i % (DIM * DIM);
    int d = r / DIM, c = r % DIM;
    g_wt[i] = w[l * DIM * DIM + c * DIM + d];
}

// ---------------- zero all per-layer stat accumulators (per graph replay) ----------
__global__ void zero_acc_kernel() {
    int i = blockIdx.x * blockDim.x + threadIdx.x;
    if (i < NLAYERS * 2 * DIM) g_acc[i] = 0.0;
}

// ---------------- KNN pass 1: per-half top-8 (strict stable insertion) ----------------
// Queries assigned to lanes in SPATIAL order (g_perm): warp lanes hold nearby
// queries, so warp-level insert triggers collapse toward per-lane triggers.
// Per-query computation (scan order, d2 chain, insertion) is bitwise identical.
__global__ void __launch_bounds__(KNN_TPB) knn_kernel() {
    __shared__ __align__(16) float sx[CAND_PER_BLOCK];
    __shared__ __align__(16) float sy[CAND_PER_BLOCK];
    __shared__ __align__(16) float sz[CAND_PER_BLOCK];
    __shared__ __align__(16) float sw[CAND_PER_BLOCK];
    int b = blockIdx.y;
    int half = blockIdx.z;
    int q = g_perm[b * NPTS + blockIdx.x * KNN_TPB + threadIdx.x];
    int base = half * CAND_PER_BLOCK;
    const float4* xb = g_xyz4 + b * NPTS;
    float4 me = xb[q];
    float nx = -2.f * me.x, ny = -2.f * me.y, nz = -2.f * me.z;
    float sqi = me.w;
    unsigned long long NX2 = f2pk(nx, nx), NY2 = f2pk(ny, ny), NZ2 = f2pk(nz, nz);
    unsigned long long SQ2 = f2pk(sqi, sqi);

    for (int t = threadIdx.x; t < CAND_PER_BLOCK; t += KNN_TPB) {
        float4 c = xb[base + t];
        sx[t] = c.x; sy[t] = c.y; sz[t] = c.z; sw[t] = c.w;
    }

    float bd[KNB];
    int   bi[KNB];
#pragma unroll
    for (int k = 0; k < KNB; k++) { bd[k] = CUDART_INF_F; bi[k] = -1; }
    __syncthreads();

#define TRYINS(dv, jv)                                                    \
    if ((dv) < bd[KNB - 1]) {                                             \
        bd[KNB - 1] = (dv); bi[KNB - 1] = (jv);                           \
        _Pragma("unroll")                                                 \
        for (int k = KNB - 1; k >= 1; k--) {                              \
            if (bd[k] < bd[k - 1]) {                                      \
                float td = bd[k]; bd[k] = bd[k - 1]; bd[k - 1] = td;      \
                int   ti = bi[k]; bi[k] = bi[k - 1]; bi[k - 1] = ti;      \
            }                                                             \
        }                                                                 \
    }

    for (int j = 0; j < CAND_PER_BLOCK; j += 4) {
        float4 x4 = *(const float4*)(sx + j);
        float4 y4 = *(const float4*)(sy + j);
        float4 z4 = *(const float4*)(sz + j);
        float4 w4 = *(const float4*)(sw + j);
        // pair 0,1  (chain bitwise-identical to scalar fmaf version)
        unsigned long long t01 = f2add(f2pk(w4.x, w4.y), SQ2);
        t01 = f2fma(f2pk(z4.x, z4.y), NZ2, t01);
        t01 = f2fma(f2pk(y4.x, y4.y), NY2, t01);
        t01 = f2fma(f2pk(x4.x, x4.y), NX2, t01);
        // pair 2,3
        unsigned long long t23 = f2add(f2pk(w4.z, w4.w), SQ2);
        t23 = f2fma(f2pk(z4.z, z4.w), NZ2, t23);
        t23 = f2fma(f2pk(y4.z, y4.w), NY2, t23);
        t23 = f2fma(f2pk(x4.z, x4.w), NX2, t23);
        float d0, d1, d2, d3;
        f2upk(d0, d1, t01);
        f2upk(d2, d3, t23);
        float m = fminf(fminf(d0, d1), fminf(d2, d3));
        if (m < bd[KNB - 1]) {
            TRYINS(d0, base + j + 0);
            TRYINS(d1, base + j + 1);
            TRYINS(d2, base + j + 2);
            TRYINS(d3, base + j + 3);
        }
    }
#undef TRYINS

    size_t o = ((size_t)(b * NPTS + q) * KNN_SPLIT + half) * KNB;
#pragma unroll
    for (int k = 0; k < KNB; k++) { g_knn_d[o + k] = bd[k]; g_knn_i[o + k] = bi[k]; }
}

// ---------------- KNN pass 2: merge the two sorted top-8 lists ----------------
// Half-0 indices are all < half-1 indices, so 'dA <= dB -> take A' preserves
// lower-index-first on ties (matches reference top_k tie order).
__global__ void knn_merge_kernel() {
    int i = blockIdx.x * blockDim.x + threadIdx.x;
    if (i >= B * NPTS) return;
    size_t o = (size_t)i * KNN_SPLIT * KNB;
    const float* dA = g_knn_d + o;
    const float* dB = dA + KNB;
    const int*   iA = g_knn_i + o;
    const int*   iB = iA + KNB;
    int a = 0, c = 0;
    int* orow = g_idx + (size_t)i * KNB;
#pragma unroll
    for (int k = 0; k < KNB; k++) {
        bool takeA = (c >= KNB) || (a < KNB && dA[a] <= dB[c]);
        orow[k] = takeA ? iA[a] : iB[c];
        if (takeA) a++; else c++;
    }
}

// ---------------- layer-0 stats: fp32 partials -> double atomics ----------------
__global__ void __launch_bounds__(256) stats0_kernel(const float* __restrict__ p) {
    int c = blockIdx.x, b = blockIdx.y;
    const float* row = p + ((size_t)b * DIM + c) * NPTS;
    float s = 0.f, q = 0.f;
    for (int i = threadIdx.x; i < NPTS; i += 256) {
        float v = row[i];
        s += v; q = fmaf(v, v, q);
    }
    __shared__ float ss[256], qq[256];
    ss[threadIdx.x] = s; qq[threadIdx.x] = q;
    __syncthreads();
    for (int o = 128; o > 0; o >>= 1) {
        if (threadIdx.x < o) { ss[threadIdx.x] += ss[threadIdx.x + o]; qq[threadIdx.x] += qq[threadIdx.x + o]; }
        __syncthreads();
    }
    if (threadIdx.x == 0) {
        atomicAdd(&g_acc[c],       (double)ss[0]);
        atomicAdd(&g_acc[DIM + c], (double)qq[0]);
    }
}

// ---------------- layer-0 prep: transpose points to point-major raw ----------------
__global__ void __launch_bounds__(256) transpose_kernel(const float* __restrict__ p,
                                                        float* __restrict__ pm) {
    __shared__ float tile[DIM][65];
    int b = blockIdx.y;
    int i0 = blockIdx.x * 64;
    int t = threadIdx.x;
#pragma unroll
    for (int k = 0; k < 16; k++) {
        int e = t + k * 256;
        int c = e >> 6, i = e & 63;
        tile[c][i] = p[((size_t)b * DIM + c) * NPTS + i0 + i];
    }
    __syncthreads();
#pragma unroll
    for (int k = 0; k < 16; k++) {
        int e = t + k * 256;
        int i = e >> 6, c = e & 63;
        pm[((size_t)b * NPTS + i0 + i) * DIM + c] = tile[c][i];
    }
}

// ==== fused layer: BN fold + gather(normalize+lrelu on the fly) + matmul + residual
//      + next-layer stats + point-major raw output ====
__global__ void __launch_bounds__(256) fused_block_kernel(
        const float* __restrict__ pin,    // channel-major raw prev (residual + output base)
        const float* __restrict__ pm_in,  // point-major raw prev
        float* __restrict__ pout,         // channel-major raw out
        float* __restrict__ pm_out,       // point-major raw out (null on last layer)
        const float* __restrict__ wt,
        const float* __restrict__ bias,
        const double* __restrict__ accin, // stats of prev raw -> scale/shift
        double* __restrict__ accout,      // stats accum for out (null on last layer)
        const float* __restrict__ gamma,
        const float* __restrict__ beta) {
    __shared__ float Wt[DIM][DIM];   // Wt[d][c]
    __shared__ float S[64][65];      // phase 1: S[i][d] = aggregated h / (K+1); phase 2: [c][i]
    __shared__ float s_sc[DIM], s_sh[DIM];
    int b = blockIdx.y;
    int i0 = blockIdx.x * 64;
    int t = threadIdx.x;

    // prologue: fold BN stats into scale/shift (identical math to old finalize/hnorm)
    if (t < DIM) {
        double s = accin[t], q = accin[DIM + t];
        double mean = s / (double)(B * NPTS);
        double var  = q / (double)(B * NPTS) - mean * mean;
        float rstd = rsqrtf((float)var + 1e-5f);
        float sc = gamma[t] * rstd;
        s_sc[t] = sc;
        s_sh[t] = beta[t] - (float)mean * sc;
    }
    // stage W^T (consumed after the post-aggregation sync)
#pragma unroll
    for (int k = 0; k < 16; k++) {
        int e = t + k * 256;
        ((float*)Wt)[e] = wt[e];
    }
    __syncthreads();   // s_sc/s_sh ready for aggregation

    // aggregation: warp handles 8 points as 4 half-warp pairs; 16 lanes x float4 = 256B row.
    // h = lrelu(raw*sc+sh) applied at gather time (bitwise-identical to precomputed h).
    int warp = t >> 5, lane = t & 31;
    int half = lane >> 4, l16 = lane & 15;
    const float inv = 1.f / (float)(KNB + 1);
    float4 sc4 = *(const float4*)&s_sc[4 * l16];
    float4 sh4 = *(const float4*)&s_sh[4 * l16];
    for (int pp = 0; pp < 8; pp += 2) {
        int il = warp * 8 + pp + half;
        int ig = i0 + il;
        const int4* ir = (const int4*)(g_idx + ((size_t)b * NPTS + ig) * KNB);
        int4 ja = ir[0], jb = ir[1];
        int js[9] = { ig, ja.x, ja.y, ja.z, ja.w, jb.x, jb.y, jb.z, jb.w };
        float a0 = 0.f, a1 = 0.f, a2 = 0.f, a3 = 0.f;
#pragma unroll
        for (int k = 0; k < 9; k++) {
            const float4* row = (const float4*)(pm_in + ((size_t)b * NPTS + js[k]) * DIM);
            float4 v = row[l16];
            float h0 = fmaf(v.x, sc4.x, sh4.x); h0 = (h0 >= 0.f) ? h0 : 0.01f * h0;
            float h1 = fmaf(v.y, sc4.y, sh4.y); h1 = (h1 >= 0.f) ? h1 : 0.01f * h1;
            float h2 = fmaf(v.z, sc4.z, sh4.z); h2 = (h2 >= 0.f) ? h2 : 0.01f * h2;
            float h3 = fmaf(v.w, sc4.w, sh4.w); h3 = (h3 >= 0.f) ? h3 : 0.01f * h3;
            a0 += h0; a1 += h1; a2 += h2; a3 += h3;
        }
        S[il][4 * l16 + 0] = a0 * inv;
        S[il][4 * l16 + 1] = a1 * inv;
        S[il][4 * l16 + 2] = a2 * inv;
        S[il][4 * l16 + 3] = a3 * inv;
    }
    __syncthreads();

    // matmul: thread handles point i = t%64, channels [c0, c0+16)
    int g  = t >> 6;
    int i  = t & 63;
    int c0 = g * 16;
    float acc[16];
#pragma unroll
    for (int j = 0; j < 16; j++) acc[j] = 0.f;
#pragma unroll 4
    for (int d = 0; d < DIM; d++) {
        float sv = S[i][d];
        const float4* wr = (const float4*)(&Wt[d][c0]);
#pragma unroll
        for (int q = 0; q < 4; q++) {
            float4 w4 = wr[q];
            acc[4 * q + 0] = fmaf(sv, w4.x, acc[4 * q + 0]);
            acc[4 * q + 1] = fmaf(sv, w4.y, acc[4 * q + 1]);
            acc[4 * q + 2] = fmaf(sv, w4.z, acc[4 * q + 2]);
            acc[4 * q + 3] = fmaf(sv, w4.w, acc[4 * q + 3]);
        }
    }
    // write channel-major outputs (bias + residual), keep values for epilogue
#pragma unroll
    for (int j = 0; j < 16; j++) {
        int c = c0 + j;
        size_t off = ((size_t)b * DIM + c) * NPTS + i0 + i;
        float v = acc[j] + bias[c] + pin[off];
        pout[off] = v;
        acc[j] = v;
    }

    if (accout != nullptr || pm_out != nullptr) {
        __syncthreads();   // all matmul reads of S done before reuse
#pragma unroll
        for (int j = 0; j < 16; j++) S[c0 + j][i] = acc[j];
        __syncthreads();

        // next-layer stats: per-channel partial sums -> global double accumulators
        if (accout != nullptr && t < DIM) {
            float s0 = 0.f, s1 = 0.f, q0 = 0.f, q1 = 0.f;
#pragma unroll
            for (int i2 = 0; i2 < 64; i2 += 2) {
                float a = S[t][i2], bb = S[t][i2 + 1];
                s0 += a; s1 += bb;
                q0 = fmaf(a, a, q0); q1 = fmaf(bb, bb, q1);
            }
            atomicAdd(&accout[t],       (double)(s0 + s1));
            atomicAdd(&accout[DIM + t], (double)(q0 + q1));
        }

        // point-major raw output (coalesced via smem)
        if (pm_out != nullptr) {
#pragma unroll
            for (int k = 0; k < 16; k++) {
                int e = t + k * 256;
                int ii = e >> 6, cc = e & 63;
                pm_out[((size_t)b * NPTS + i0 + ii) * DIM + cc] = S[cc][ii];
            }
        }
    }
}

// ---------------- launch ----------------
extern "C" void kernel_launch(void* const* d_in, const int* in_sizes, int n_in,
                              void* d_out, int out_size) {
    const float* xyz    = (const float*)d_in[0];
    const float* points = (const float*)d_in[1];
    const float* conv_w = (const float*)d_in[2];
    const float* conv_b = (const float*)d_in[3];
    const float* gamma  = (const float*)d_in[4];
    const float* beta   = (const float*)d_in[5];
    float* out = (float*)d_out;

    float *bufA, *bufB, *wtp, *pm0, *pm1;
    double* accp;
    cudaGetSymbolAddress((void**)&bufA, g_bufA);
    cudaGetSymbolAddress((void**)&bufB, g_bufB);
    cudaGetSymbolAddress((void**)&wtp,  g_wt);
    cudaGetSymbolAddress((void**)&pm0,  g_pm0);
    cudaGetSymbolAddress((void**)&pm1,  g_pm1);
    cudaGetSymbolAddress((void**)&accp, g_acc);

    zero_acc_kernel<<<(NLAYERS * 2 * DIM + 255) / 256, 256>>>();
    zero_hist_kernel<<<(B * NBINS + 255) / 256, 256>>>();
    prep_xyz_kernel<<<(B * NPTS + 255) / 256, 256>>>(xyz);
    prep_wt_kernel<<<(NLAYERS * DIM * DIM + 255) / 256, 256>>>(conv_w);
    prefix_kernel<<<B, NBINS>>>();
    scatter_kernel<<<(B * NPTS + 255) / 256, 256>>>();
    knn_kernel<<<dim3(NPTS / KNN_TPB, B, KNN_SPLIT), KNN_TPB>>>();
    knn_merge_kernel<<<(B * NPTS + 255) / 256, 256>>>();
    stats0_kernel<<<dim3(DIM, B), 256>>>(points);
    transpose_kernel<<<dim3(NPTS / 64, B), 256>>>(points, pm0);

    const float* cur = points;
    const float* pm_cur = pm0;
    for (int l = 0; l < NLAYERS; l++) {
        bool last = (l == NLAYERS - 1);
        float* nxt   = last ? out : ((l & 1) ? bufB : bufA);
        float* pm_nx = last ? nullptr : ((l & 1) ? pm0 : pm1);
        double* accout = last ? nullptr : (accp + (size_t)(l + 1) * 2 * DIM);
        fused_block_kernel<<<dim3(NPTS / 64, B), 256>>>(
            cur, pm_cur, nxt, pm_nx,
            wtp + (size_t)l * DIM * DIM, conv_b + l * DIM,
            accp + (size_t)l * 2 * DIM, accout,
            gamma + l * DIM, beta + l * DIM);
        cur = nxt;
        pm_cur = pm_nx;
    }
}

// round 17
// speedup vs baseline: 1.4183x; 1.0281x over previous
#include <cuda_runtime.h>
#include <math_constants.h>

#define B 8
#define NPTS 4096
#define DIM 64
#define KNB 8
#define NLAYERS 12

#define KNN_SPLIT 2
#define CAND_PER_BLOCK (NPTS / KNN_SPLIT)   // 2048
#define KNN_TPB 128
#define NBINS 512                            // 8x8x8 morton bins

// fused-layer dynamic smem partition (floats)
#define FB_WT   0                            // Wt[64][64]
#define FB_S    (FB_WT + DIM * DIM)          // S[64][65]
#define FB_R    (FB_S + 64 * 65)             // R[64][68] (16B-aligned rows)
#define FB_SC   (FB_R + 64 * 68)             // s_sc[64]
#define FB_SH   (FB_SC + DIM)                // s_sh[64]
#define FB_TOT  (FB_SH + DIM)
#define FUSED_SMEM (FB_TOT * 4)

// ---------------- device-global scratch (no dynamic allocation allowed) -------------
__device__ float4 g_xyz4[B * NPTS];                     // (x,y,z,|x|^2) per point
__device__ int    g_idx [B * NPTS * KNB];               // knn indices [b][n][k]
__device__ float  g_knn_d[B * NPTS * KNN_SPLIT * KNB];  // partial top-8 distances
__device__ int    g_knn_i[B * NPTS * KNN_SPLIT * KNB];  // partial top-8 indices
__device__ int    g_key [B * NPTS];                     // spatial bin key per point
__device__ int    g_hist[B * NBINS];                    // per-batch bin histogram
__device__ int    g_off [B * NBINS];                    // per-batch bin offsets (consumed)
__device__ int    g_perm[B * NPTS];                     // spatially-sorted query order
__device__ float  g_pm0 [B * NPTS * DIM];               // raw features, point-major (ping)
__device__ float  g_pm1 [B * NPTS * DIM];               // raw features, point-major (pong)
__device__ float  g_wt  [NLAYERS * DIM * DIM];          // W^T per layer: wt[d][c] = w[c][d]
__device__ double g_acc[NLAYERS * 2 * DIM];             // per-layer [l][c]=sum, [l][DIM+c]=sumsq

// ---------------- packed f32x2 helpers (per-lane rounding == scalar fmaf/add) -------
__device__ __forceinline__ unsigned long long f2pk(float lo, float hi) {
    unsigned long long r;
    asm("mov.b64 %0, {%1, %2};" : "=l"(r) : "f"(lo), "f"(hi));
    return r;
}
__device__ __forceinline__ void f2upk(float& lo, float& hi, unsigned long long v) {
    asm("mov.b64 {%0, %1}, %2;" : "=f"(lo), "=f"(hi) : "l"(v));
}
__device__ __forceinline__ unsigned long long f2add(unsigned long long a, unsigned long long b) {
    unsigned long long r;
    asm("add.rn.f32x2 %0, %1, %2;" : "=l"(r) : "l"(a), "l"(b));
    return r;
}
__device__ __forceinline__ unsigned long long f2fma(unsigned long long a, unsigned long long b,
                                                    unsigned long long c) {
    unsigned long long r;
    asm("fma.rn.f32x2 %0, %1, %2, %3;" : "=l"(r) : "l"(a), "l"(b), "l"(c));
    return r;
}

// ---------------- prep: pack xyz + squared norm; spatial bin key + histogram --------
__global__ void zero_hist_kernel() {
    int i = blockIdx.x * blockDim.x + threadIdx.x;
    if (i < B * NBINS) g_hist[i] = 0;
}

__device__ __forceinline__ int morton9(int a, int b, int c) {
    int m = 0;
#pragma unroll
    for (int k = 0; k < 3; k++) {
        m |= ((a >> k) & 1) << (3 * k + 2);
        m |= ((b >> k) & 1) << (3 * k + 1);
        m |= ((c >> k) & 1) << (3 * k + 0);
    }
    return m;
}

__global__ void prep_xyz_kernel(const float* __restrict__ xyz) {
    int i = blockIdx.x * blockDim.x + threadIdx.x;
    if (i >= B * NPTS) return;
    int b = i / NPTS, p = i % NPTS;
    const float* base = xyz + (size_t)b * 3 * NPTS;
    float x = base[p], y = base[NPTS + p], z = base[2 * NPTS + p];
    float sq = x * x + y * y + z * z;
    g_xyz4[i] = make_float4(x, y, z, sq);
    int cx = min(7, max(0, (int)((x + 2.0f) * 2.0f)));
    int cy = min(7, max(0, (int)((y + 2.0f) * 2.0f)));
    int cz = min(7, max(0, (int)((z + 2.0f) * 2.0f)));
    int key = morton9(cx, cy, cz);
    g_key[i] = key;
    atomicAdd(&g_hist[b * NBINS + key], 1);
}

// per-batch exclusive prefix over NBINS bins (one block per batch)
__global__ void __launch_bounds__(NBINS) prefix_kernel() {
    __shared__ int s[NBINS];
    int b = blockIdx.x, t = threadIdx.x;
    int orig = g_hist[b * NBINS + t];
    s[t] = orig;
    __syncthreads();
    for (int o = 1; o < NBINS; o <<= 1) {
        int u = (t >= o) ? s[t - o] : 0;
        __syncthreads();
        s[t] += u;
        __syncthreads();
    }
    g_off[b * NBINS + t] = s[t] - orig;   // exclusive
}

// scatter points into spatial order (intra-bin order nondeterministic — harmless,
// since each query's KNN result is independent of which lane computes it)
__global__ void scatter_kernel() {
    int i = blockIdx.x * blockDim.x + threadIdx.x;
    if (i >= B * NPTS) return;
    int b = i / NPTS, p = i % NPTS;
    int key = g_key[i];
    int pos = atomicAdd(&g_off[b * NBINS + key], 1);
    g_perm[b * NPTS + pos] = p;
}

// ---------------- prep: transpose conv weights ----------------
__global__ void prep_wt_kernel(const float* __restrict__ w) {
    int i = blockIdx.x * blockDim.x + threadIdx.x;
    if (i >= NLAYERS * DIM * DIM) return;
    int l = i / (DIM * DIM), r = i % (DIM * DIM);
    int d = r / DIM, c = r % DIM;
    g_wt[i] = w[l * DIM * DIM + c * DIM + d];
}

// ---------------- zero all per-layer stat accumulators (per graph replay) ----------
__global__ void zero_acc_kernel() {
    int i = blockIdx.x * blockDim.x + threadIdx.x;
    if (i < NLAYERS * 2 * DIM) g_acc[i] = 0.0;
}

// ---------------- KNN pass 1: per-half top-8 (strict stable insertion) ----------------
// Queries assigned to lanes in SPATIAL order (g_perm): warp lanes hold nearby
// queries, so warp-level insert triggers collapse toward per-lane triggers.
// Per-query computation (scan order, d2 chain, insertion) is bitwise identical.
__global__ void __launch_bounds__(KNN_TPB) knn_kernel() {
    __shared__ __align__(16) float sx[CAND_PER_BLOCK];
    __shared__ __align__(16) float sy[CAND_PER_BLOCK];
    __shared__ __align__(16) float sz[CAND_PER_BLOCK];
    __shared__ __align__(16) float sw[CAND_PER_BLOCK];
    int b = blockIdx.y;
    int half = blockIdx.z;
    int q = g_perm[b * NPTS + blockIdx.x * KNN_TPB + threadIdx.x];
    int base = half * CAND_PER_BLOCK;
    const float4* xb = g_xyz4 + b * NPTS;
    float4 me = xb[q];
    float nx = -2.f * me.x, ny = -2.f * me.y, nz = -2.f * me.z;
    float sqi = me.w;
    unsigned long long NX2 = f2pk(nx, nx), NY2 = f2pk(ny, ny), NZ2 = f2pk(nz, nz);
    unsigned long long SQ2 = f2pk(sqi, sqi);

    for (int t = threadIdx.x; t < CAND_PER_BLOCK; t += KNN_TPB) {
        float4 c = xb[base + t];
        sx[t] = c.x; sy[t] = c.y; sz[t] = c.z; sw[t] = c.w;
    }

    float bd[KNB];
    int   bi[KNB];
#pragma unroll
    for (int k = 0; k < KNB; k++) { bd[k] = CUDART_INF_F; bi[k] = -1; }
    __syncthreads();

#define TRYINS(dv, jv)                                                    \
    if ((dv) < bd[KNB - 1]) {                                             \
        bd[KNB - 1] = (dv); bi[KNB - 1] = (jv);                           \
        _Pragma("unroll")                                                 \
        for (int k = KNB - 1; k >= 1; k--) {                              \
            if (bd[k] < bd[k - 1]) {                                      \
                float td = bd[k]; bd[k] = bd[k - 1]; bd[k - 1] = td;      \
                int   ti = bi[k]; bi[k] = bi[k - 1]; bi[k - 1] = ti;      \
            }                                                             \
        }                                                                 \
    }

    for (int j = 0; j < CAND_PER_BLOCK; j += 4) {
        float4 x4 = *(const float4*)(sx + j);
        float4 y4 = *(const float4*)(sy + j);
        float4 z4 = *(const float4*)(sz + j);
        float4 w4 = *(const float4*)(sw + j);
        // pair 0,1  (chain bitwise-identical to scalar fmaf version)
        unsigned long long t01 = f2add(f2pk(w4.x, w4.y), SQ2);
        t01 = f2fma(f2pk(z4.x, z4.y), NZ2, t01);
        t01 = f2fma(f2pk(y4.x, y4.y), NY2, t01);
        t01 = f2fma(f2pk(x4.x, x4.y), NX2, t01);
        // pair 2,3
        unsigned long long t23 = f2add(f2pk(w4.z, w4.w), SQ2);
        t23 = f2fma(f2pk(z4.z, z4.w), NZ2, t23);
        t23 = f2fma(f2pk(y4.z, y4.w), NY2, t23);
        t23 = f2fma(f2pk(x4.z, x4.w), NX2, t23);
        float d0, d1, d2, d3;
        f2upk(d0, d1, t01);
        f2upk(d2, d3, t23);
        float m = fminf(fminf(d0, d1), fminf(d2, d3));
        if (m < bd[KNB - 1]) {
            TRYINS(d0, base + j + 0);
            TRYINS(d1, base + j + 1);
            TRYINS(d2, base + j + 2);
            TRYINS(d3, base + j + 3);
        }
    }
#undef TRYINS

    size_t o = ((size_t)(b * NPTS + q) * KNN_SPLIT + half) * KNB;
#pragma unroll
    for (int k = 0; k < KNB; k++) { g_knn_d[o + k] = bd[k]; g_knn_i[o + k] = bi[k]; }
}

// ---------------- KNN pass 2: merge the two sorted top-8 lists ----------------
// Half-0 indices are all < half-1 indices, so 'dA <= dB -> take A' preserves
// lower-index-first on ties (matches reference top_k tie order).
__global__ void knn_merge_kernel() {
    int i = blockIdx.x * blockDim.x + threadIdx.x;
    if (i >= B * NPTS) return;
    size_t o = (size_t)i * KNN_SPLIT * KNB;
    const float* dA = g_knn_d + o;
    const float* dB = dA + KNB;
    const int*   iA = g_knn_i + o;
    const int*   iB = iA + KNB;
    int a = 0, c = 0;
    int* orow = g_idx + (size_t)i * KNB;
#pragma unroll
    for (int k = 0; k < KNB; k++) {
        bool takeA = (c >= KNB) || (a < KNB && dA[a] <= dB[c]);
        orow[k] = takeA ? iA[a] : iB[c];
        if (takeA) a++; else c++;
    }
}

// ---------------- layer-0 stats: fp32 partials -> double atomics ----------------
__global__ void __launch_bounds__(256) stats0_kernel(const float* __restrict__ p) {
    int c = blockIdx.x, b = blockIdx.y;
    const float* row = p + ((size_t)b * DIM + c) * NPTS;
    float s = 0.f, q = 0.f;
    for (int i = threadIdx.x; i < NPTS; i += 256) {
        float v = row[i];
        s += v; q = fmaf(v, v, q);
    }
    __shared__ float ss[256], qq[256];
    ss[threadIdx.x] = s; qq[threadIdx.x] = q;
    __syncthreads();
    for (int o = 128; o > 0; o >>= 1) {
        if (threadIdx.x < o) { ss[threadIdx.x] += ss[threadIdx.x + o]; qq[threadIdx.x] += qq[threadIdx.x + o]; }
        __syncthreads();
    }
    if (threadIdx.x == 0) {
        atomicAdd(&g_acc[c],       (double)ss[0]);
        atomicAdd(&g_acc[DIM + c], (double)qq[0]);
    }
}

// ---------------- layer-0 prep: transpose points to point-major raw ----------------
__global__ void __launch_bounds__(256) transpose_kernel(const float* __restrict__ p,
                                                        float* __restrict__ pm) {
    __shared__ float tile[DIM][65];
    int b = blockIdx.y;
    int i0 = blockIdx.x * 64;
    int t = threadIdx.x;
#pragma unroll
    for (int k = 0; k < 16; k++) {
        int e = t + k * 256;
        int c = e >> 6, i = e & 63;
        tile[c][i] = p[((size_t)b * DIM + c) * NPTS + i0 + i];
    }
    __syncthreads();
#pragma unroll
    for (int k = 0; k < 16; k++) {
        int e = t + k * 256;
        int i = e >> 6, c = e & 63;
        pm[((size_t)b * NPTS + i0 + i) * DIM + c] = tile[c][i];
    }
}

// ==== fused layer: BN fold + gather(normalize+lrelu on the fly) + matmul + residual
//      + next-layer stats + point-major raw output. Residual stashed in smem (R)
//      from the center-row load during aggregation — no channel-major buffers. ====
__global__ void __launch_bounds__(256) fused_block_kernel(
        const float* __restrict__ pm_in,  // point-major raw prev (gather + residual)
        float* __restrict__ pout,         // channel-major final out (last layer only)
        float* __restrict__ pm_out,       // point-major raw out (null on last layer)
        const float* __restrict__ wt,
        const float* __restrict__ bias,
        const double* __restrict__ accin, // stats of prev raw -> scale/shift
        double* __restrict__ accout,      // stats accum for out (null on last layer)
        const float* __restrict__ gamma,
        const float* __restrict__ beta) {
    extern __shared__ float sm[];
    float* Wt   = sm + FB_WT;    // Wt[d*64 + c]
    float* S    = sm + FB_S;     // S[i*65 + d] phase1; S[c*65 + i] phase2
    float* R    = sm + FB_R;     // R[i*68 + c]  raw center rows (residual)
    float* s_sc = sm + FB_SC;
    float* s_sh = sm + FB_SH;
    int b = blockIdx.y;
    int i0 = blockIdx.x * 64;
    int t = threadIdx.x;

    // prologue: fold BN stats into scale/shift (identical math to before)
    if (t < DIM) {
        double s = accin[t], q = accin[DIM + t];
        double mean = s / (double)(B * NPTS);
        double var  = q / (double)(B * NPTS) - mean * mean;
        float rstd = rsqrtf((float)var + 1e-5f);
        float sc = gamma[t] * rstd;
        s_sc[t] = sc;
        s_sh[t] = beta[t] - (float)mean * sc;
    }
    // stage W^T (consumed after the post-aggregation sync)
#pragma unroll
    for (int k = 0; k < 16; k++) {
        int e = t + k * 256;
        Wt[e] = wt[e];
    }
    __syncthreads();   // s_sc/s_sh ready for aggregation

    // aggregation: warp handles 8 points as 4 half-warp pairs; 16 lanes x float4 = 256B row.
    // h = lrelu(raw*sc+sh) applied at gather time (bitwise-identical to precomputed h).
    // k==0 center row raw values are stashed into R for the residual (no global re-read).
    int warp = t >> 5, lane = t & 31;
    int half = lane >> 4, l16 = lane & 15;
    const float inv = 1.f / (float)(KNB + 1);
    float4 sc4 = *(const float4*)&s_sc[4 * l16];
    float4 sh4 = *(const float4*)&s_sh[4 * l16];
    for (int pp = 0; pp < 8; pp += 2) {
        int il = warp * 8 + pp + half;
        int ig = i0 + il;
        const int4* ir = (const int4*)(g_idx + ((size_t)b * NPTS + ig) * KNB);
        int4 ja = ir[0], jb = ir[1];
        int js[9] = { ig, ja.x, ja.y, ja.z, ja.w, jb.x, jb.y, jb.z, jb.w };
        float a0 = 0.f, a1 = 0.f, a2 = 0.f, a3 = 0.f;
#pragma unroll
        for (int k = 0; k < 9; k++) {
            const float4* row = (const float4*)(pm_in + ((size_t)b * NPTS + js[k]) * DIM);
            float4 v = row[l16];
            if (k == 0) *(float4*)&R[il * 68 + 4 * l16] = v;   // raw center -> residual tile
            float h0 = fmaf(v.x, sc4.x, sh4.x); h0 = (h0 >= 0.f) ? h0 : 0.01f * h0;
            float h1 = fmaf(v.y, sc4.y, sh4.y); h1 = (h1 >= 0.f) ? h1 : 0.01f * h1;
            float h2 = fmaf(v.z, sc4.z, sh4.z); h2 = (h2 >= 0.f) ? h2 : 0.01f * h2;
            float h3 = fmaf(v.w, sc4.w, sh4.w); h3 = (h3 >= 0.f) ? h3 : 0.01f * h3;
            a0 += h0; a1 += h1; a2 += h2; a3 += h3;
        }
        S[il * 65 + 4 * l16 + 0] = a0 * inv;
        S[il * 65 + 4 * l16 + 1] = a1 * inv;
        S[il * 65 + 4 * l16 + 2] = a2 * inv;
        S[il * 65 + 4 * l16 + 3] = a3 * inv;
    }
    __syncthreads();

    // matmul: thread handles point i = t%64, channels [c0, c0+16)
    int g  = t >> 6;
    int i  = t & 63;
    int c0 = g * 16;
    float acc[16];
#pragma unroll
    for (int j = 0; j < 16; j++) acc[j] = 0.f;
#pragma unroll 4
    for (int d = 0; d < DIM; d++) {
        float sv = S[i * 65 + d];
        const float4* wr = (const float4*)(&Wt[d * DIM + c0]);
#pragma unroll
        for (int q = 0; q < 4; q++) {
            float4 w4 = wr[q];
            acc[4 * q + 0] = fmaf(sv, w4.x, acc[4 * q + 0]);
            acc[4 * q + 1] = fmaf(sv, w4.y, acc[4 * q + 1]);
            acc[4 * q + 2] = fmaf(sv, w4.z, acc[4 * q + 2]);
            acc[4 * q + 3] = fmaf(sv, w4.w, acc[4 * q + 3]);
        }
    }
    // combine: v = (conv + bias) + raw residual  (same order/values as before)
    {
        const float4* rr = (const float4*)&R[i * 68 + c0];
        const float4* bb = (const float4*)(bias + c0);
#pragma unroll
        for (int q = 0; q < 4; q++) {
            float4 r4 = rr[q];
            float4 b4 = bb[q];
            acc[4 * q + 0] = (acc[4 * q + 0] + b4.x) + r4.x;
            acc[4 * q + 1] = (acc[4 * q + 1] + b4.y) + r4.y;
            acc[4 * q + 2] = (acc[4 * q + 2] + b4.z) + r4.z;
            acc[4 * q + 3] = (acc[4 * q + 3] + b4.w) + r4.w;
        }
    }

    if (pout != nullptr) {
        // last layer: channel-major output, coalesced across i
#pragma unroll
        for (int j = 0; j < 16; j++) {
            int c = c0 + j;
            pout[((size_t)b * DIM + c) * NPTS + i0 + i] = acc[j];
        }
    }

    if (pm_out != nullptr) {
        __syncthreads();   // all matmul reads of S done before reuse
#pragma unroll
        for (int j = 0; j < 16; j++) S[(c0 + j) * 65 + i] = acc[j];
        __syncthreads();

        // next-layer stats: per-channel partial sums -> global double accumulators
        if (accout != nullptr && t < DIM) {
            float s0 = 0.f, s1 = 0.f, q0 = 0.f, q1 = 0.f;
#pragma unroll
            for (int i2 = 0; i2 < 64; i2 += 2) {
                float a = S[t * 65 + i2], bb2 = S[t * 65 + i2 + 1];
                s0 += a; s1 += bb2;
                q0 = fmaf(a, a, q0); q1 = fmaf(bb2, bb2, q1);
            }
            atomicAdd(&accout[t],       (double)(s0 + s1));
            atomicAdd(&accout[DIM + t], (double)(q0 + q1));
        }

        // point-major raw output (coalesced via smem)
#pragma unroll
        for (int k = 0; k < 16; k++) {
            int e = t + k * 256;
            int ii = e >> 6, cc = e & 63;
            pm_out[((size_t)b * NPTS + i0 + ii) * DIM + cc] = S[cc * 65 + ii];
        }
    }
}

// ---------------- launch ----------------
extern "C" void kernel_launch(void* const* d_in, const int* in_sizes, int n_in,
                              void* d_out, int out_size) {
    const float* xyz    = (const float*)d_in[0];
    const float* points = (const float*)d_in[1];
    const float* conv_w = (const float*)d_in[2];
    const float* conv_b = (const float*)d_in[3];
    const float* gamma  = (const float*)d_in[4];
    const float* beta   = (const float*)d_in[5];
    float* out = (float*)d_out;

    float *wtp, *pm0, *pm1;
    double* accp;
    cudaGetSymbolAddress((void**)&wtp,  g_wt);
    cudaGetSymbolAddress((void**)&pm0,  g_pm0);
    cudaGetSymbolAddress((void**)&pm1,  g_pm1);
    cudaGetSymbolAddress((void**)&accp, g_acc);

    cudaFuncSetAttribute(fused_block_kernel,
                         cudaFuncAttributeMaxDynamicSharedMemorySize, FUSED_SMEM);

    zero_acc_kernel<<<(NLAYERS * 2 * DIM + 255) / 256, 256>>>();
    zero_hist_kernel<<<(B * NBINS + 255) / 256, 256>>>();
    prep_xyz_kernel<<<(B * NPTS + 255) / 256, 256>>>(xyz);
    prep_wt_kernel<<<(NLAYERS * DIM * DIM + 255) / 256, 256>>>(conv_w);
    prefix_kernel<<<B, NBINS>>>();
    scatter_kernel<<<(B * NPTS + 255) / 256, 256>>>();
    knn_kernel<<<dim3(NPTS / KNN_TPB, B, KNN_SPLIT), KNN_TPB>>>();
    knn_merge_kernel<<<(B * NPTS + 255) / 256, 256>>>();
    stats0_kernel<<<dim3(DIM, B), 256>>>(points);
    transpose_kernel<<<dim3(NPTS / 64, B), 256>>>(points, pm0);

    const float* pm_cur = pm0;
    for (int l = 0; l < NLAYERS; l++) {
        bool last = (l == NLAYERS - 1);
        float* pout  = last ? out : nullptr;
        float* pm_nx = last ? nullptr : ((l & 1) ? pm0 : pm1);
        double* accout = last ? nullptr : (accp + (size_t)(l + 1) * 2 * DIM);
        fused_block_kernel<<<dim3(NPTS / 64, B), 256, FUSED_SMEM>>>(
            pm_cur, pout, pm_nx,
            wtp + (size_t)l * DIM * DIM, conv_b + l * DIM,
            accp + (size_t)l * 2 * DIM, accout,
            gamma + l * DIM, beta + l * DIM);
        pm_cur = pm_nx;
    }
}